// round 1
// baseline (speedup 1.0000x reference)
#include <cuda_runtime.h>

// BatchedStructureDecoder: out[g] = sigmoid(Z_g @ Z_g^T), G=128, N=512, D=256.
// Inputs per metadata order: d_in[0]=z (float32, 65536x256), d_in[1]=batch (int32,
// contiguous-sorted, exactly 512 nodes/graph -> mask is all-true, ignored),
// d_in[2]=num_graphs, d_in[3]=max_nodes (fixed; hardcoded).
//
// Strategy (round 1): SIMT SGEMM using packed fma.rn.f32x2 (2x fp32 FFMA issue
// rate on sm_103a) + symmetry: only tile-pairs (it<=jt) computed, transpose
// written from registers (warp-level stores form full 32B sectors).

namespace {
constexpr int NN = 512;   // nodes per graph
constexpr int ND = 256;   // latent dim
constexpr int BM = 128;   // tile M == tile N
constexpr int BK = 16;
constexpr int NKT = ND / BK;  // 16 k-stages
constexpr int NPAIR = 10;     // upper-triangular 4x4 tile pairs
}

__constant__ int c_it[NPAIR] = {0,0,0,0,1,1,1,2,2,3};
__constant__ int c_jt[NPAIR] = {0,1,2,3,1,2,3,2,3,3};

__device__ __forceinline__ unsigned long long pk2(float lo, float hi) {
    unsigned long long r;
    asm("mov.b64 %0, {%1, %2};" : "=l"(r) : "f"(lo), "f"(hi));
    return r;
}
__device__ __forceinline__ void upk2(unsigned long long v, float& lo, float& hi) {
    asm("mov.b64 {%0, %1}, %2;" : "=f"(lo), "=f"(hi) : "l"(v));
}
__device__ __forceinline__ void fma2(unsigned long long& acc,
                                     unsigned long long a, unsigned long long b) {
    asm("fma.rn.f32x2 %0, %1, %2, %0;" : "+l"(acc) : "l"(a), "l"(b));
}

__device__ __forceinline__ float fast_sigmoid(float x) {
    // 1 / (1 + exp(-x)); MUFU.EX2 + MUFU.RCP, rel err ~2^-21 — fine for 1e-3.
    float e = __expf(-x);
    return __fdividef(1.0f, 1.0f + e);
}

__global__ __launch_bounds__(256, 2)
void decoder_kernel(const float* __restrict__ z, float* __restrict__ out) {
    __shared__ float As[2][BK][BM + 4];
    __shared__ float Bs[2][BK][BM + 4];

    const int g  = blockIdx.y;
    const int it = c_it[blockIdx.x];
    const int jt = c_jt[blockIdx.x];

    const float* Zg = z + (size_t)g * NN * ND;
    float*       Og = out + (size_t)g * NN * NN;

    const int tid = threadIdx.x;
    const int tx  = tid & 15;   // 0..15 (cols)
    const int ty  = tid >> 4;   // 0..15 (rows)

    // loader mapping: 512 float4 per tile per operand; thread handles f=tid, f=tid+256
    const int lrow = tid >> 2;        // 0..63
    const int lk   = (tid & 3) * 4;   // 0,4,8,12

    const float* Ag = Zg + (size_t)(it * BM) * ND;
    const float* Bg = Zg + (size_t)(jt * BM) * ND;

    unsigned long long acc[8][4];
#pragma unroll
    for (int i = 0; i < 8; i++)
#pragma unroll
        for (int j = 0; j < 4; j++) acc[i][j] = 0ull;

    float4 a_ld0, a_ld1, b_ld0, b_ld1;

    // ---- prologue: load k-stage 0 ----
    a_ld0 = *(const float4*)(Ag + (size_t)lrow * ND + lk);
    a_ld1 = *(const float4*)(Ag + (size_t)(64 + lrow) * ND + lk);
    b_ld0 = *(const float4*)(Bg + (size_t)lrow * ND + lk);
    b_ld1 = *(const float4*)(Bg + (size_t)(64 + lrow) * ND + lk);

    As[0][lk+0][lrow] = a_ld0.x; As[0][lk+1][lrow] = a_ld0.y;
    As[0][lk+2][lrow] = a_ld0.z; As[0][lk+3][lrow] = a_ld0.w;
    As[0][lk+0][64+lrow] = a_ld1.x; As[0][lk+1][64+lrow] = a_ld1.y;
    As[0][lk+2][64+lrow] = a_ld1.z; As[0][lk+3][64+lrow] = a_ld1.w;
    Bs[0][lk+0][lrow] = b_ld0.x; Bs[0][lk+1][lrow] = b_ld0.y;
    Bs[0][lk+2][lrow] = b_ld0.z; Bs[0][lk+3][lrow] = b_ld0.w;
    Bs[0][lk+0][64+lrow] = b_ld1.x; Bs[0][lk+1][64+lrow] = b_ld1.y;
    Bs[0][lk+2][64+lrow] = b_ld1.z; Bs[0][lk+3][64+lrow] = b_ld1.w;
    __syncthreads();

    int buf = 0;
    for (int kt = 0; kt < NKT; kt++) {
        // prefetch next stage into registers
        if (kt + 1 < NKT) {
            const int k0 = (kt + 1) * BK + lk;
            a_ld0 = *(const float4*)(Ag + (size_t)lrow * ND + k0);
            a_ld1 = *(const float4*)(Ag + (size_t)(64 + lrow) * ND + k0);
            b_ld0 = *(const float4*)(Bg + (size_t)lrow * ND + k0);
            b_ld1 = *(const float4*)(Bg + (size_t)(64 + lrow) * ND + k0);
        }

#pragma unroll
        for (int k = 0; k < BK; k++) {
            float4 a0 = *(const float4*)&As[buf][k][ty * 4];
            float4 a1 = *(const float4*)&As[buf][k][64 + ty * 4];
            float4 b0 = *(const float4*)&Bs[buf][k][tx * 4];
            float4 b1 = *(const float4*)&Bs[buf][k][64 + tx * 4];

            unsigned long long bp0 = pk2(b0.x, b0.y);
            unsigned long long bp1 = pk2(b0.z, b0.w);
            unsigned long long bp2 = pk2(b1.x, b1.y);
            unsigned long long bp3 = pk2(b1.z, b1.w);

            float av[8] = {a0.x, a0.y, a0.z, a0.w, a1.x, a1.y, a1.z, a1.w};
#pragma unroll
            for (int i = 0; i < 8; i++) {
                unsigned long long ap = pk2(av[i], av[i]);
                fma2(acc[i][0], ap, bp0);
                fma2(acc[i][1], ap, bp1);
                fma2(acc[i][2], ap, bp2);
                fma2(acc[i][3], ap, bp3);
            }
        }

        if (kt + 1 < NKT) {
            const int nb = buf ^ 1;
            As[nb][lk+0][lrow] = a_ld0.x; As[nb][lk+1][lrow] = a_ld0.y;
            As[nb][lk+2][lrow] = a_ld0.z; As[nb][lk+3][lrow] = a_ld0.w;
            As[nb][lk+0][64+lrow] = a_ld1.x; As[nb][lk+1][64+lrow] = a_ld1.y;
            As[nb][lk+2][64+lrow] = a_ld1.z; As[nb][lk+3][64+lrow] = a_ld1.w;
            Bs[nb][lk+0][lrow] = b_ld0.x; Bs[nb][lk+1][lrow] = b_ld0.y;
            Bs[nb][lk+2][lrow] = b_ld0.z; Bs[nb][lk+3][lrow] = b_ld0.w;
            Bs[nb][lk+0][64+lrow] = b_ld1.x; Bs[nb][lk+1][64+lrow] = b_ld1.y;
            Bs[nb][lk+2][64+lrow] = b_ld1.z; Bs[nb][lk+3][64+lrow] = b_ld1.w;
        }
        buf ^= 1;
        __syncthreads();
    }

    // ---- epilogue: unpack + sigmoid ----
    float cres[8][8];
#pragma unroll
    for (int i = 0; i < 8; i++)
#pragma unroll
        for (int jp = 0; jp < 4; jp++) {
            float lo, hi;
            upk2(acc[i][jp], lo, hi);
            cres[i][2 * jp]     = fast_sigmoid(lo);
            cres[i][2 * jp + 1] = fast_sigmoid(hi);
        }

    const int rbase = it * BM;
    const int cbase = jt * BM;

    // direct store of tile (it, jt)
#pragma unroll
    for (int i = 0; i < 8; i++) {
        const int r = (i < 4) ? (ty * 4 + i) : (64 + ty * 4 + (i - 4));
        float4 w0 = make_float4(cres[i][0], cres[i][1], cres[i][2], cres[i][3]);
        float4 w1 = make_float4(cres[i][4], cres[i][5], cres[i][6], cres[i][7]);
        float* p = Og + (size_t)(rbase + r) * NN + cbase;
        *(float4*)(p + tx * 4)      = w0;
        *(float4*)(p + 64 + tx * 4) = w1;
    }

    // transposed store of tile (jt, it) — symmetry of sigmoid(Z Z^T)
    if (it != jt) {
#pragma unroll
        for (int j = 0; j < 8; j++) {
            const int c = (j < 4) ? (tx * 4 + j) : (64 + tx * 4 + (j - 4));
            float4 w0 = make_float4(cres[0][j], cres[1][j], cres[2][j], cres[3][j]);
            float4 w1 = make_float4(cres[4][j], cres[5][j], cres[6][j], cres[7][j]);
            float* p = Og + (size_t)(cbase + c) * NN + rbase;
            *(float4*)(p + ty * 4)      = w0;
            *(float4*)(p + 64 + ty * 4) = w1;
        }
    }
}

extern "C" void kernel_launch(void* const* d_in, const int* in_sizes, int n_in,
                              void* d_out, int out_size) {
    const float* z = (const float*)d_in[0];
    float* out = (float*)d_out;
    dim3 grid(NPAIR, 128);
    decoder_kernel<<<grid, 256>>>(z, out);
}

// round 3
// speedup vs baseline: 1.3680x; 1.3680x over previous
#include <cuda_runtime.h>
#include <cuda_bf16.h>
#include <cstdint>

// out[g] = sigmoid(Z_g @ Z_g^T), G=128, N=512, D=256, fp32.
// Round 3: tcgen05 unavailable (harness compiles via compute_103 virtual arch,
// which rejects sm_103a-gated PTX). Use classic mma.sync.m16n8k16 bf16
// (sm_80+ feature) with hi/lo split for fp32-grade precision:
//   Z Z^T ~= Zh Zh^T + Zh Zl^T + Zl Zh^T   (drop Zl Zl^T ~ 2^-18)
// Pre-pass converts z -> bf16 hi/lo once into __device__ scratch.
// GEMM: 128x128 tile/CTA, symmetry over 4x4 tile pairs (10 of 16), transposed
// tile written from the same result.

namespace {
constexpr int NN = 512;
constexpr int ND = 256;
constexpr int BM = 128;
constexpr int NPAIR = 10;
constexpr int SROW = 72;              // bf16 elems per smem row (144B, conflict-free LDSM)
constexpr int SMAT = 128 * SROW * 2;  // 18432 B per operand tile
constexpr int SMEM_DYN = 4 * SMAT;    // 73728 B (Ah, Al, Bh, Bl)
}

__constant__ int c_it[NPAIR] = {0,0,0,0,1,1,1,2,2,3};
__constant__ int c_jt[NPAIR] = {0,1,2,3,1,2,3,2,3,3};

__device__ __align__(16) __nv_bfloat16 g_zh[(size_t)128 * 512 * 256];  // 32MB
__device__ __align__(16) __nv_bfloat16 g_zl[(size_t)128 * 512 * 256];  // 32MB

__device__ __forceinline__ uint32_t cvta_smem(const void* p) {
    uint32_t a;
    asm("{ .reg .u64 t; cvta.to.shared.u64 t, %1; cvt.u32.u64 %0, t; }"
        : "=r"(a) : "l"(p));
    return a;
}

__device__ __forceinline__ void ldsm4(uint32_t* r, uint32_t addr) {
    asm volatile("ldmatrix.sync.aligned.m8n8.x4.shared.b16 {%0,%1,%2,%3}, [%4];"
                 : "=r"(r[0]), "=r"(r[1]), "=r"(r[2]), "=r"(r[3]) : "r"(addr));
}

__device__ __forceinline__ void mma16816(float* c, const uint32_t* a,
                                         uint32_t b0, uint32_t b1) {
    asm volatile(
        "mma.sync.aligned.m16n8k16.row.col.f32.bf16.bf16.f32 "
        "{%0,%1,%2,%3}, {%4,%5,%6,%7}, {%8,%9}, {%0,%1,%2,%3};"
        : "+f"(c[0]), "+f"(c[1]), "+f"(c[2]), "+f"(c[3])
        : "r"(a[0]), "r"(a[1]), "r"(a[2]), "r"(a[3]), "r"(b0), "r"(b1));
}

__device__ __forceinline__ float fast_sigmoid(float x) {
    float e = __expf(-x);
    return __fdividef(1.0f, 1.0f + e);
}

// ---------------- pre-pass: fp32 -> bf16 hi/lo ----------------
__global__ void convert_kernel(const float* __restrict__ z) {
    size_t i = (size_t)blockIdx.x * blockDim.x + threadIdx.x;  // one float4
    float4 v = ((const float4*)z)[i];
    __nv_bfloat162 h01 = __floats2bfloat162_rn(v.x, v.y);
    __nv_bfloat162 h23 = __floats2bfloat162_rn(v.z, v.w);
    float2 f01 = __bfloat1622float2(h01);
    float2 f23 = __bfloat1622float2(h23);
    __nv_bfloat162 l01 = __floats2bfloat162_rn(v.x - f01.x, v.y - f01.y);
    __nv_bfloat162 l23 = __floats2bfloat162_rn(v.z - f23.x, v.w - f23.y);
    ((uint2*)g_zh)[i] = make_uint2(*(uint32_t*)&h01, *(uint32_t*)&h23);
    ((uint2*)g_zl)[i] = make_uint2(*(uint32_t*)&l01, *(uint32_t*)&l23);
}

// ---------------- GEMM + sigmoid ----------------
__global__ __launch_bounds__(256, 2)
void gemm_kernel(float* __restrict__ out) {
    extern __shared__ char smem[];
    const int tid  = threadIdx.x;
    const int lane = tid & 31;
    const int wid  = tid >> 5;
    const int wm   = wid & 3;   // m-block (32 rows)
    const int wn   = wid >> 2;  // n-block (64 cols)

    const int g  = blockIdx.y;
    const int it = c_it[blockIdx.x];
    const int jt = c_jt[blockIdx.x];

    const __nv_bfloat16* __restrict__ Ah = g_zh + ((size_t)g * NN + it * BM) * ND;
    const __nv_bfloat16* __restrict__ Al = g_zl + ((size_t)g * NN + it * BM) * ND;
    const __nv_bfloat16* __restrict__ Bh = g_zh + ((size_t)g * NN + jt * BM) * ND;
    const __nv_bfloat16* __restrict__ Bl = g_zl + ((size_t)g * NN + jt * BM) * ND;

    const uint32_t s32 = cvta_smem(smem);

    float c[2][8][4];
#pragma unroll
    for (int mt = 0; mt < 2; mt++)
#pragma unroll
        for (int nt = 0; nt < 8; nt++)
#pragma unroll
            for (int q = 0; q < 4; q++) c[mt][nt][q] = 0.0f;

    // ldmatrix per-thread base offsets (bytes)
    const uint32_t aoff = (uint32_t)((wm * 32 + (lane & 15)) * (SROW * 2) +
                                     ((lane >> 4) & 1) * 16);
    const uint32_t boff = (uint32_t)((wn * 64 + ((lane >> 4) << 3) + (lane & 7)) * (SROW * 2) +
                                     ((lane >> 3) & 1) * 16);

    for (int ch = 0; ch < 4; ch++) {
        __syncthreads();
        // cp.async: 4 matrices x 128 rows x 4x16B -> 16 transfers/thread
#pragma unroll
        for (int mat = 0; mat < 4; mat++) {
            const __nv_bfloat16* src =
                (mat == 0) ? Ah : (mat == 1) ? Al : (mat == 2) ? Bh : Bl;
            const uint32_t sb = s32 + mat * SMAT;
#pragma unroll
            for (int i2 = 0; i2 < 4; i2++) {
                const int idx2 = tid + 256 * i2;
                const int row  = idx2 >> 3;
                const int seg  = idx2 & 7;
                const uint32_t dst = sb + (uint32_t)(row * (SROW * 2) + seg * 16);
                const void* s = src + (size_t)row * ND + ch * 64 + seg * 8;
                asm volatile("cp.async.ca.shared.global [%0], [%1], 16;"
                             :: "r"(dst), "l"(s) : "memory");
            }
        }
        asm volatile("cp.async.commit_group;" ::: "memory");
        asm volatile("cp.async.wait_group 0;" ::: "memory");
        __syncthreads();

#pragma unroll
        for (int ks = 0; ks < 4; ks++) {
            uint32_t ah[2][4], al[2][4], b[16];
            const uint32_t kofs = ks * 32;
#pragma unroll
            for (int mt = 0; mt < 2; mt++) {
                ldsm4(ah[mt], s32 + 0 * SMAT + aoff + mt * 16 * (SROW * 2) + kofs);
                ldsm4(al[mt], s32 + 1 * SMAT + aoff + mt * 16 * (SROW * 2) + kofs);
            }
#pragma unroll
            for (int bt = 0; bt < 4; bt++)
                ldsm4(&b[bt * 4], s32 + 2 * SMAT + boff + bt * 16 * (SROW * 2) + kofs);
#pragma unroll
            for (int mt = 0; mt < 2; mt++)
#pragma unroll
                for (int nt = 0; nt < 8; nt++) {
                    const uint32_t b0 = b[(nt >> 1) * 4 + (nt & 1) * 2];
                    const uint32_t b1 = b[(nt >> 1) * 4 + (nt & 1) * 2 + 1];
                    mma16816(c[mt][nt], ah[mt], b0, b1);
                    mma16816(c[mt][nt], al[mt], b0, b1);
                }
            // reload b regs with B-lo, third product Ah*Bl
#pragma unroll
            for (int bt = 0; bt < 4; bt++)
                ldsm4(&b[bt * 4], s32 + 3 * SMAT + boff + bt * 16 * (SROW * 2) + kofs);
#pragma unroll
            for (int mt = 0; mt < 2; mt++)
#pragma unroll
                for (int nt = 0; nt < 8; nt++) {
                    const uint32_t b0 = b[(nt >> 1) * 4 + (nt & 1) * 2];
                    const uint32_t b1 = b[(nt >> 1) * 4 + (nt & 1) * 2 + 1];
                    mma16816(c[mt][nt], ah[mt], b0, b1);
                }
        }
    }

    // ---- epilogue: sigmoid -> smem -> coalesced direct + transposed stores ----
    __syncthreads();
    float* sC = (float*)smem;  // [128][132] fp32, 67584B <= 73728B
    const int r0  = wm * 32 + (lane >> 2);
    const int cn0 = wn * 64 + (lane & 3) * 2;
#pragma unroll
    for (int mt = 0; mt < 2; mt++)
#pragma unroll
        for (int nt = 0; nt < 8; nt++) {
            const int r  = r0 + mt * 16;
            const int cc = cn0 + nt * 8;
            sC[r * 132 + cc]           = fast_sigmoid(c[mt][nt][0]);
            sC[r * 132 + cc + 1]       = fast_sigmoid(c[mt][nt][1]);
            sC[(r + 8) * 132 + cc]     = fast_sigmoid(c[mt][nt][2]);
            sC[(r + 8) * 132 + cc + 1] = fast_sigmoid(c[mt][nt][3]);
        }
    __syncthreads();

    const int rbase = it * BM, cbase = jt * BM;
    {
        const int r    = tid >> 1;
        const int colh = (tid & 1) * 64;
        float* dst = out + ((size_t)g * NN + rbase + r) * NN + cbase + colh;
        const float* srcr = sC + r * 132 + colh;
#pragma unroll
        for (int q = 0; q < 16; q++)
            ((float4*)dst)[q] = ((const float4*)srcr)[q];
    }
    if (it != jt) {
        const int cc = tid >> 1;
        const int rh = (tid & 1) * 64;
        float* dst = out + ((size_t)g * NN + cbase + cc) * NN + rbase + rh;
#pragma unroll
        for (int q = 0; q < 16; q++) {
            float4 w;
            w.x = sC[(rh + q * 4 + 0) * 132 + cc];
            w.y = sC[(rh + q * 4 + 1) * 132 + cc];
            w.z = sC[(rh + q * 4 + 2) * 132 + cc];
            w.w = sC[(rh + q * 4 + 3) * 132 + cc];
            ((float4*)dst)[q] = w;
        }
    }
}

extern "C" void kernel_launch(void* const* d_in, const int* in_sizes, int n_in,
                              void* d_out, int out_size) {
    const float* z = (const float*)d_in[0];
    float* out = (float*)d_out;
    // 128*512*256 / 4 = 4,194,304 float4s / 256 threads = 16384 blocks
    convert_kernel<<<16384, 256>>>(z);
    cudaFuncSetAttribute(gemm_kernel, cudaFuncAttributeMaxDynamicSharedMemorySize,
                         SMEM_DYN);
    dim3 grid(NPAIR, 128);
    gemm_kernel<<<grid, 256, SMEM_DYN>>>(out);
}

// round 4
// speedup vs baseline: 1.4017x; 1.0247x over previous
#include <cuda_runtime.h>
#include <cuda_bf16.h>
#include <cstdint>

// out[g] = sigmoid(Z_g @ Z_g^T), G=128, N=512, D=256, fp32.
// mma.sync.m16n8k16 bf16, hi/lo split (hh + hl + lh products).
// R4: 3-stage cp.async pipeline, K-chunk=32, swizzled 64B rows (no padding),
// symmetry over 10 of 16 tile pairs, transposed tile stored via smem.

namespace {
constexpr int NN = 512;
constexpr int ND = 256;
constexpr int BM = 128;
constexpr int NPAIR = 10;
constexpr int BKC = 32;                  // k per chunk
constexpr int NCH = ND / BKC;            // 8 chunks
constexpr int SMATC = BM * BKC * 2;      // 8192 B per operand per chunk
constexpr int SSTAGE = 4 * SMATC;        // 32768 B (Ah, Al, Bh, Bl)
constexpr int NSTAGE = 3;
constexpr int SMEM_DYN = NSTAGE * SSTAGE;  // 98304 B
}

__constant__ int c_it[NPAIR] = {0,0,0,0,1,1,1,2,2,3};
__constant__ int c_jt[NPAIR] = {0,1,2,3,1,2,3,2,3,3};

__device__ __align__(16) __nv_bfloat16 g_zh[(size_t)128 * 512 * 256];  // 32MB
__device__ __align__(16) __nv_bfloat16 g_zl[(size_t)128 * 512 * 256];  // 32MB

__device__ __forceinline__ uint32_t cvta_smem(const void* p) {
    uint32_t a;
    asm("{ .reg .u64 t; cvta.to.shared.u64 t, %1; cvt.u32.u64 %0, t; }"
        : "=r"(a) : "l"(p));
    return a;
}

// swizzled byte offset within one operand mat: 64B rows, 4 x 16B segs
__device__ __forceinline__ uint32_t swz(int row, int seg) {
    return (uint32_t)(row * 64 + ((seg ^ ((row >> 1) & 3)) << 4));
}

__device__ __forceinline__ void ldsm4(uint32_t* r, uint32_t addr) {
    asm volatile("ldmatrix.sync.aligned.m8n8.x4.shared.b16 {%0,%1,%2,%3}, [%4];"
                 : "=r"(r[0]), "=r"(r[1]), "=r"(r[2]), "=r"(r[3]) : "r"(addr));
}

__device__ __forceinline__ void mma16816(float* c, const uint32_t* a,
                                         uint32_t b0, uint32_t b1) {
    asm volatile(
        "mma.sync.aligned.m16n8k16.row.col.f32.bf16.bf16.f32 "
        "{%0,%1,%2,%3}, {%4,%5,%6,%7}, {%8,%9}, {%0,%1,%2,%3};"
        : "+f"(c[0]), "+f"(c[1]), "+f"(c[2]), "+f"(c[3])
        : "r"(a[0]), "r"(a[1]), "r"(a[2]), "r"(a[3]), "r"(b0), "r"(b1));
}

__device__ __forceinline__ float fast_sigmoid(float x) {
    float e = __expf(-x);
    return __fdividef(1.0f, 1.0f + e);
}

// ---------------- pre-pass: fp32 -> bf16 hi/lo ----------------
__global__ __launch_bounds__(256)
void convert_kernel(const float* __restrict__ z) {
    size_t base = ((size_t)blockIdx.x * blockDim.x + threadIdx.x) * 2;
#pragma unroll
    for (int u = 0; u < 2; u++) {
        size_t i = base + u;
        float4 v = ((const float4*)z)[i];
        __nv_bfloat162 h01 = __floats2bfloat162_rn(v.x, v.y);
        __nv_bfloat162 h23 = __floats2bfloat162_rn(v.z, v.w);
        float2 f01 = __bfloat1622float2(h01);
        float2 f23 = __bfloat1622float2(h23);
        __nv_bfloat162 l01 = __floats2bfloat162_rn(v.x - f01.x, v.y - f01.y);
        __nv_bfloat162 l23 = __floats2bfloat162_rn(v.z - f23.x, v.w - f23.y);
        ((uint2*)g_zh)[i] = make_uint2(*(uint32_t*)&h01, *(uint32_t*)&h23);
        ((uint2*)g_zl)[i] = make_uint2(*(uint32_t*)&l01, *(uint32_t*)&l23);
    }
}

// ---------------- GEMM + sigmoid ----------------
__global__ __launch_bounds__(256, 2)
void gemm_kernel(float* __restrict__ out) {
    extern __shared__ char smem[];
    const int tid  = threadIdx.x;
    const int lane = tid & 31;
    const int wid  = tid >> 5;
    const int wm   = wid & 3;   // 32-row block
    const int wn   = wid >> 2;  // 64-col block

    const int g  = blockIdx.y;
    const int it = c_it[blockIdx.x];
    const int jt = c_jt[blockIdx.x];

    const __nv_bfloat16* __restrict__ Ah = g_zh + ((size_t)g * NN + it * BM) * ND;
    const __nv_bfloat16* __restrict__ Al = g_zl + ((size_t)g * NN + it * BM) * ND;
    const __nv_bfloat16* __restrict__ Bh = g_zh + ((size_t)g * NN + jt * BM) * ND;
    const __nv_bfloat16* __restrict__ Bl = g_zl + ((size_t)g * NN + jt * BM) * ND;

    const uint32_t s32 = cvta_smem(smem);

    // loader mapping: idx = tid + 256*i -> row = idx>>2, seg = idx&3 (2 per mat)
    const int ld_row0 = tid >> 2;
    const int ld_seg  = tid & 3;

    float c[2][8][4];
#pragma unroll
    for (int mt = 0; mt < 2; mt++)
#pragma unroll
        for (int nt = 0; nt < 8; nt++)
#pragma unroll
            for (int q = 0; q < 4; q++) c[mt][nt][q] = 0.0f;

    const int la_r = lane & 15, la_s = lane >> 4;
    const int lb_r = ((lane >> 4) << 3) + (lane & 7), lb_s = (lane >> 3) & 1;

    auto issue_chunk = [&](int ch) {
        const uint32_t sb = s32 + (ch % NSTAGE) * SSTAGE;
        const int kofs = ch * BKC;
#pragma unroll
        for (int mat = 0; mat < 4; mat++) {
            const __nv_bfloat16* src =
                (mat == 0) ? Ah : (mat == 1) ? Al : (mat == 2) ? Bh : Bl;
            const uint32_t mb = sb + mat * SMATC;
#pragma unroll
            for (int i2 = 0; i2 < 2; i2++) {
                const int row = ld_row0 + 64 * i2;
                const uint32_t dst = mb + swz(row, ld_seg);
                const void* s = src + (size_t)row * ND + kofs + ld_seg * 8;
                asm volatile("cp.async.cg.shared.global [%0], [%1], 16;"
                             :: "r"(dst), "l"(s) : "memory");
            }
        }
    };

    // prologue: chunks 0,1
    issue_chunk(0);
    asm volatile("cp.async.commit_group;" ::: "memory");
    issue_chunk(1);
    asm volatile("cp.async.commit_group;" ::: "memory");

    for (int ch = 0; ch < NCH; ch++) {
        if (ch + NSTAGE - 1 < NCH) issue_chunk(ch + NSTAGE - 1);
        asm volatile("cp.async.commit_group;" ::: "memory");
        asm volatile("cp.async.wait_group %0;" :: "n"(NSTAGE - 1) : "memory");
        __syncthreads();

        const uint32_t sb = s32 + (ch % NSTAGE) * SSTAGE;
#pragma unroll
        for (int h = 0; h < 2; h++) {
            uint32_t ah[2][4], al[2][4], b[16];
#pragma unroll
            for (int mt = 0; mt < 2; mt++) {
                const int row = wm * 32 + mt * 16 + la_r;
                const int seg = 2 * h + la_s;
                ldsm4(ah[mt], sb + 0 * SMATC + swz(row, seg));
                ldsm4(al[mt], sb + 1 * SMATC + swz(row, seg));
            }
#pragma unroll
            for (int bt = 0; bt < 4; bt++) {
                const int row = wn * 64 + bt * 16 + lb_r;
                ldsm4(&b[bt * 4], sb + 2 * SMATC + swz(row, 2 * h + lb_s));
            }
#pragma unroll
            for (int mt = 0; mt < 2; mt++)
#pragma unroll
                for (int nt = 0; nt < 8; nt++) {
                    const uint32_t b0 = b[(nt >> 1) * 4 + (nt & 1) * 2];
                    const uint32_t b1 = b[(nt >> 1) * 4 + (nt & 1) * 2 + 1];
                    mma16816(c[mt][nt], ah[mt], b0, b1);
                    mma16816(c[mt][nt], al[mt], b0, b1);
                }
#pragma unroll
            for (int bt = 0; bt < 4; bt++) {
                const int row = wn * 64 + bt * 16 + lb_r;
                ldsm4(&b[bt * 4], sb + 3 * SMATC + swz(row, 2 * h + lb_s));
            }
#pragma unroll
            for (int mt = 0; mt < 2; mt++)
#pragma unroll
                for (int nt = 0; nt < 8; nt++) {
                    const uint32_t b0 = b[(nt >> 1) * 4 + (nt & 1) * 2];
                    const uint32_t b1 = b[(nt >> 1) * 4 + (nt & 1) * 2 + 1];
                    mma16816(c[mt][nt], ah[mt], b0, b1);
                }
        }
        __syncthreads();
    }

    // ---- epilogue: sigmoid -> smem -> coalesced direct + transposed stores ----
    float* sC = (float*)smem;  // [128][132] fp32 = 67584 B <= 98304 B
    const int r0  = wm * 32 + (lane >> 2);
    const int cn0 = wn * 64 + (lane & 3) * 2;
#pragma unroll
    for (int mt = 0; mt < 2; mt++)
#pragma unroll
        for (int nt = 0; nt < 8; nt++) {
            const int r  = r0 + mt * 16;
            const int cc = cn0 + nt * 8;
            sC[r * 132 + cc]           = fast_sigmoid(c[mt][nt][0]);
            sC[r * 132 + cc + 1]       = fast_sigmoid(c[mt][nt][1]);
            sC[(r + 8) * 132 + cc]     = fast_sigmoid(c[mt][nt][2]);
            sC[(r + 8) * 132 + cc + 1] = fast_sigmoid(c[mt][nt][3]);
        }
    __syncthreads();

    const int rbase = it * BM, cbase = jt * BM;
    {
        const int r    = tid >> 1;
        const int colh = (tid & 1) * 64;
        float* dst = out + ((size_t)g * NN + rbase + r) * NN + cbase + colh;
        const float* srcr = sC + r * 132 + colh;
#pragma unroll
        for (int q = 0; q < 16; q++)
            ((float4*)dst)[q] = ((const float4*)srcr)[q];
    }
    if (it != jt) {
        const int cc = tid >> 1;
        const int rh = (tid & 1) * 64;
        float* dst = out + ((size_t)g * NN + cbase + cc) * NN + rbase + rh;
#pragma unroll
        for (int q = 0; q < 16; q++) {
            float4 w;
            w.x = sC[(rh + q * 4 + 0) * 132 + cc];
            w.y = sC[(rh + q * 4 + 1) * 132 + cc];
            w.z = sC[(rh + q * 4 + 2) * 132 + cc];
            w.w = sC[(rh + q * 4 + 3) * 132 + cc];
            ((float4*)dst)[q] = w;
        }
    }
}

extern "C" void kernel_launch(void* const* d_in, const int* in_sizes, int n_in,
                              void* d_out, int out_size) {
    const float* z = (const float*)d_in[0];
    float* out = (float*)d_out;
    // 4,194,304 float4s / (256 threads * 2) = 8192 blocks
    convert_kernel<<<8192, 256>>>(z);
    cudaFuncSetAttribute(gemm_kernel, cudaFuncAttributeMaxDynamicSharedMemorySize,
                         SMEM_DYN);
    dim3 grid(NPAIR, 128);
    gemm_kernel<<<grid, 256, SMEM_DYN>>>(out);
}